// round 2
// baseline (speedup 1.0000x reference)
#include <cuda_runtime.h>

#define IMG_H 512
#define IMG_W 512
#define TX 32
#define TY 64
#define HALO 5
#define IN_W (TX + 2*HALO)   // 42
#define IN_H (TY + 2*HALO)   // 74
#define SXS 43               // sx/sy row stride (conflict-free for 8row x 4cg warp shape)
#define HS  33               // H row stride (conflict-free writes: r + 8*cg distinct mod 32)
#define NT  256

#define C1 1.0e-4f
#define C2 9.0e-4f
#define EPSV 1.0e-8f

// Normalized 1D Gaussian, sigma=1.5, window 11.
// Compile-time constants -> conv FMAs become FFMA-imm (rt_SMSP=1, 2x tput vs 3-reg).
__device__ constexpr float GW[11] = {
    0.00102838f, 0.00759876f, 0.03600077f, 0.10936069f, 0.21300553f,
    0.26601172f,
    0.21300553f, 0.10936069f, 0.03600077f, 0.00759876f, 0.00102838f
};

__global__ void zero_out_kernel(float* out) { out[0] = 0.0f; }

__global__ __launch_bounds__(NT) void ssim_kernel(
    const float* __restrict__ x, const float* __restrict__ y,
    float* __restrict__ out, float inv_n)
{
    extern __shared__ float smem[];
    float* sx = smem;                         // IN_H * SXS
    float* sy = sx + IN_H * SXS;
    float* H0 = sy + IN_H * SXS;              // 5 maps, each IN_H * HS
    float* H1 = H0 + IN_H * HS;
    float* H2 = H1 + IN_H * HS;
    float* H3 = H2 + IN_H * HS;
    float* H4 = H3 + IN_H * HS;
    float* red = H4 + IN_H * HS;              // 8 floats

    const int tid = threadIdx.x;
    const int x0 = blockIdx.x * TX - HALO;
    const int y0 = blockIdx.y * TY - HALO;
    const size_t imgoff = (size_t)blockIdx.z * (IMG_H * IMG_W);
    const float* xb = x + imgoff;
    const float* yb = y + imgoff;

    // ---- Phase 1: load halo tiles (zero pad = SAME padding semantics) ----
    for (int idx = tid; idx < IN_H * IN_W; idx += NT) {
        int r = idx / IN_W;
        int c = idx - r * IN_W;
        int gy = y0 + r, gx = x0 + c;
        float xv = 0.0f, yv = 0.0f;
        if (gy >= 0 && gy < IMG_H && gx >= 0 && gx < IMG_W) {
            int g = gy * IMG_W + gx;
            xv = __ldg(xb + g);
            yv = __ldg(yb + g);
        }
        sx[r * SXS + c] = xv;
        sy[r * SXS + c] = yv;
    }
    __syncthreads();

    // ---- Phase 2: horizontal pass, scatter form, 8 cols per thread-unit ----
    // unit u -> (row = u>>2, colgroup = u&3). 74 rows * 4 groups = 296 units.
    for (int u = tid; u < IN_H * 4; u += NT) {
        int row = u >> 2;
        int cg  = u & 3;
        float s0[8], s1[8], s2[8], s3[8], s4[8];
        #pragma unroll
        for (int k = 0; k < 8; k++) { s0[k]=0.f; s1[k]=0.f; s2[k]=0.f; s3[k]=0.f; s4[k]=0.f; }
        const float* px = sx + row * SXS + cg * 8;
        const float* py = sy + row * SXS + cg * 8;
        #pragma unroll
        for (int i = 0; i < 18; i++) {
            float xv = px[i];
            float yv = py[i];
            float xx = xv * xv, yy = yv * yv, xy = xv * yv;
            #pragma unroll
            for (int k = 0; k < 8; k++) {
                if (i - k >= 0 && i - k <= 10) {   // compile-time filtered
                    const float w = GW[i - k];
                    s0[k] = fmaf(xv, w, s0[k]);
                    s1[k] = fmaf(yv, w, s1[k]);
                    s2[k] = fmaf(xx, w, s2[k]);
                    s3[k] = fmaf(yy, w, s3[k]);
                    s4[k] = fmaf(xy, w, s4[k]);
                }
            }
        }
        int hb = row * HS + cg * 8;
        #pragma unroll
        for (int k = 0; k < 8; k++) {
            H0[hb + k] = s0[k];
            H1[hb + k] = s1[k];
            H2[hb + k] = s2[k];
            H3[hb + k] = s3[k];
            H4[hb + k] = s4[k];
        }
    }
    __syncthreads();

    // ---- Phase 3: vertical pass + SSIM, 8 rows per thread ----
    const int c  = tid & 31;
    const int rg = tid >> 5;     // 0..7 -> rows rg*8 .. rg*8+7
    float m0[8], m1[8], m2[8], m3[8], m4[8];
    #pragma unroll
    for (int k = 0; k < 8; k++) { m0[k]=0.f; m1[k]=0.f; m2[k]=0.f; m3[k]=0.f; m4[k]=0.f; }
    const int rbase = rg * 8;
    #pragma unroll
    for (int j = 0; j < 18; j++) {
        int hb = (rbase + j) * HS + c;
        float h0 = H0[hb], h1 = H1[hb], h2 = H2[hb], h3 = H3[hb], h4 = H4[hb];
        #pragma unroll
        for (int k = 0; k < 8; k++) {
            if (j - k >= 0 && j - k <= 10) {
                const float w = GW[j - k];
                m0[k] = fmaf(h0, w, m0[k]);
                m1[k] = fmaf(h1, w, m1[k]);
                m2[k] = fmaf(h2, w, m2[k]);
                m3[k] = fmaf(h3, w, m3[k]);
                m4[k] = fmaf(h4, w, m4[k]);
            }
        }
    }

    float lsum = 0.0f;
    #pragma unroll
    for (int k = 0; k < 8; k++) {
        float mux = m0[k], muy = m1[k];
        float mux2 = mux * mux, muy2 = muy * muy, muxy = mux * muy;
        float sxv  = m2[k] - mux2;
        float syv  = m3[k] - muy2;
        float sxyv = m4[k] - muxy;
        float n = (2.0f * muxy + C1) * (2.0f * sxyv + C2);
        float d = (mux2 + muy2 + C1) * (sxv + syv + C2) + EPSV;
        float v = (1.0f + n / d) * 0.5f;
        v = fminf(fmaxf(v, 0.0f), 1.0f);
        lsum += v;
    }

    // ---- Reduction: warp shuffle -> smem -> block -> atomic ----
    #pragma unroll
    for (int off = 16; off > 0; off >>= 1)
        lsum += __shfl_xor_sync(0xFFFFFFFFu, lsum, off);
    if ((tid & 31) == 0) red[tid >> 5] = lsum;
    __syncthreads();
    if (tid == 0) {
        float t = 0.0f;
        #pragma unroll
        for (int w = 0; w < 8; w++) t += red[w];
        atomicAdd(out, t * inv_n);
    }
}

extern "C" void kernel_launch(void* const* d_in, const int* in_sizes, int n_in,
                              void* d_out, int out_size)
{
    const float* x = (const float*)d_in[0];
    const float* y = (const float*)d_in[1];
    float* out = (float*)d_out;

    const int smem_bytes = (2 * IN_H * SXS + 5 * IN_H * HS + 8) * (int)sizeof(float);
    // No-stream host API: cannot invalidate graph capture; idempotent.
    cudaFuncSetAttribute(ssim_kernel, cudaFuncAttributeMaxDynamicSharedMemorySize, smem_bytes);

    zero_out_kernel<<<1, 1>>>(out);

    dim3 grid(IMG_W / TX, IMG_H / TY, 16 * 3);   // 16 x 8 x 48
    const float inv_n = 1.0f / (float)(16 * 3 * IMG_H * IMG_W);
    ssim_kernel<<<grid, NT, smem_bytes>>>(x, y, out, inv_n);
}

// round 3
// speedup vs baseline: 1.3340x; 1.3340x over previous
#include <cuda_runtime.h>

#define IMG_H 512
#define IMG_W 512
#define TX 32
#define TY 32
#define HALO 5
#define IN_W 42              // TX + 2*HALO
#define IN_H 42              // TY + 2*HALO
#define SP 43                // sxy row stride in 8B pair-slots (43 ≡ 11 mod 16, conflict-free)
#define HP 33                // H row stride (pair-slots for H01/H23, floats for H4)
#define NT 256

#define C1V 1.0e-4f
#define C2V 9.0e-4f
#define EPSV 1.0e-8f

typedef unsigned long long ull;

// Normalized 1D Gaussian, sigma=1.5, window 11. Symmetric: GW[d] == GW[10-d].
__device__ constexpr float GW[11] = {
    0.00102838f, 0.00759876f, 0.03600077f, 0.10936069f, 0.21300553f,
    0.26601172f,
    0.21300553f, 0.10936069f, 0.03600077f, 0.00759876f, 0.00102838f
};

__device__ __forceinline__ ull pack2(float a, float b) {
    ull r; asm("mov.b64 %0, {%1, %2};" : "=l"(r) : "f"(a), "f"(b)); return r;
}
__device__ __forceinline__ void unpack2(ull v, float& a, float& b) {
    asm("mov.b64 {%0, %1}, %2;" : "=f"(a), "=f"(b) : "l"(v));
}
__device__ __forceinline__ ull mul2(ull a, ull b) {
    ull r; asm("mul.rn.f32x2 %0, %1, %2;" : "=l"(r) : "l"(a), "l"(b)); return r;
}
__device__ __forceinline__ void fma2(ull& d, ull a, ull b) {
    asm("fma.rn.f32x2 %0, %1, %2, %0;" : "+l"(d) : "l"(a), "l"(b));
}

__global__ void zero_out_kernel(float* out) { out[0] = 0.0f; }

__global__ __launch_bounds__(NT, 4) void ssim_kernel(
    const float* __restrict__ x, const float* __restrict__ y,
    float* __restrict__ out, float inv_n)
{
    // 42,200 B static SMEM (< 48KB default)
    __shared__ float smem[IN_H * SP * 2 + IN_H * HP * 5 + 8];
    ull*   sxy = (ull*)smem;                                   // IN_H*SP pair-slots (x,y)
    ull*   H01 = (ull*)(smem + IN_H * SP * 2);                 // IN_H*HP pairs (Hx, Hy)
    ull*   H23 = (ull*)(smem + IN_H * SP * 2 + IN_H * HP * 2); // IN_H*HP pairs (Hxx, Hyy)
    float* H4f = smem + IN_H * SP * 2 + IN_H * HP * 4;         // IN_H*HP floats (Hxy)
    float* red = smem + IN_H * SP * 2 + IN_H * HP * 5;         // 8 floats

    const int tid = threadIdx.x;
    const int x0 = blockIdx.x * TX - HALO;
    const int y0 = blockIdx.y * TY - HALO;
    const size_t imgoff = (size_t)blockIdx.z * (IMG_H * IMG_W);
    const float* xb = x + imgoff;
    const float* yb = y + imgoff;

    // Weight pairs (w, w): only 6 distinct by symmetry.
    ull wp[6];
    #pragma unroll
    for (int j = 0; j < 6; j++) wp[j] = pack2(GW[j], GW[j]);

    // ---- Phase 1: load halo tile, interleave (x,y) pairs (zero pad = SAME) ----
    for (int idx = tid; idx < IN_H * IN_W; idx += NT) {
        int r = idx / IN_W;
        int c = idx - r * IN_W;
        int gy = y0 + r, gx = x0 + c;
        float xv = 0.0f, yv = 0.0f;
        if (gy >= 0 && gy < IMG_H && gx >= 0 && gx < IMG_W) {
            int g = gy * IMG_W + gx;
            xv = __ldg(xb + g);
            yv = __ldg(yb + g);
        }
        sxy[r * SP + c] = pack2(xv, yv);
    }
    __syncthreads();

    // ---- Phase 2: horizontal pass, scatter form, packed maps ----
    // unit u -> cg = u/42 (4-col group), row = u%42 (row-fast: conflict-free LDS.64)
    for (int u = tid; u < IN_H * 8; u += NT) {
        int cg  = u / IN_H;
        int row = u - cg * IN_H;
        const ull* pin = sxy + row * SP + cg * 4;
        ull s01[4], s23[4]; float s4[4];
        #pragma unroll
        for (int k = 0; k < 4; k++) { s01[k] = 0ULL; s23[k] = 0ULL; s4[k] = 0.0f; }
        #pragma unroll
        for (int i = 0; i < 14; i++) {
            ull v = pin[i];
            float vx, vy; unpack2(v, vx, vy);
            ull sq = mul2(v, v);          // (x^2, y^2)
            float xy = vx * vy;
            #pragma unroll
            for (int k = 0; k < 4; k++) {
                const int d = i - k;
                if (d >= 0 && d <= 10) {  // compile-time filtered
                    fma2(s01[k], v,  wp[d < 6 ? d : 10 - d]);
                    fma2(s23[k], sq, wp[d < 6 ? d : 10 - d]);
                    s4[k] = fmaf(xy, GW[d], s4[k]);
                }
            }
        }
        const int hb = row * HP + cg * 4;
        #pragma unroll
        for (int k = 0; k < 4; k++) {
            H01[hb + k] = s01[k];
            H23[hb + k] = s23[k];
            H4f[hb + k] = s4[k];
        }
    }
    __syncthreads();

    // ---- Phase 3: vertical pass + SSIM, 4 rows per thread ----
    const int c  = tid & 31;
    const int rbase = (tid >> 5) * 4;
    ull m01[4], m23[4]; float m4v[4];
    #pragma unroll
    for (int k = 0; k < 4; k++) { m01[k] = 0ULL; m23[k] = 0ULL; m4v[k] = 0.0f; }
    #pragma unroll
    for (int j = 0; j < 14; j++) {
        const int hb = (rbase + j) * HP + c;
        ull h01 = H01[hb];
        ull h23 = H23[hb];
        float h4 = H4f[hb];
        #pragma unroll
        for (int k = 0; k < 4; k++) {
            const int d = j - k;
            if (d >= 0 && d <= 10) {
                fma2(m01[k], h01, wp[d < 6 ? d : 10 - d]);
                fma2(m23[k], h23, wp[d < 6 ? d : 10 - d]);
                m4v[k] = fmaf(h4, GW[d], m4v[k]);
            }
        }
    }

    float lsum = 0.0f;
    #pragma unroll
    for (int k = 0; k < 4; k++) {
        float mux, muy, exx, eyy;
        unpack2(m01[k], mux, muy);
        unpack2(m23[k], exx, eyy);
        float exy = m4v[k];
        float mux2 = mux * mux, muy2 = muy * muy, muxy = mux * muy;
        float sxv  = exx - mux2;
        float syv  = eyy - muy2;
        float sxyv = exy - muxy;
        float n = (2.0f * muxy + C1V) * (2.0f * sxyv + C2V);
        float d = (mux2 + muy2 + C1V) * (sxv + syv + C2V) + EPSV;
        float v = (1.0f + __fdividef(n, d)) * 0.5f;
        v = fminf(fmaxf(v, 0.0f), 1.0f);
        lsum += v;
    }

    // ---- Reduction: warp shuffle -> smem -> block -> atomic ----
    #pragma unroll
    for (int off = 16; off > 0; off >>= 1)
        lsum += __shfl_xor_sync(0xFFFFFFFFu, lsum, off);
    if ((tid & 31) == 0) red[tid >> 5] = lsum;
    __syncthreads();
    if (tid == 0) {
        float t = 0.0f;
        #pragma unroll
        for (int w = 0; w < 8; w++) t += red[w];
        atomicAdd(out, t * inv_n);
    }
}

extern "C" void kernel_launch(void* const* d_in, const int* in_sizes, int n_in,
                              void* d_out, int out_size)
{
    const float* x = (const float*)d_in[0];
    const float* y = (const float*)d_in[1];
    float* out = (float*)d_out;

    zero_out_kernel<<<1, 1>>>(out);

    dim3 grid(IMG_W / TX, IMG_H / TY, 16 * 3);   // 16 x 16 x 48
    const float inv_n = 1.0f / (float)(16 * 3 * IMG_H * IMG_W);
    ssim_kernel<<<grid, NT>>>(x, y, out, inv_n);
}

// round 4
// speedup vs baseline: 1.4425x; 1.0814x over previous
#include <cuda_runtime.h>

#define IMG_H 512
#define IMG_W 512
#define TX 32
#define TY 32
#define HALO 5
#define IN_W 42              // TX + 2*HALO
#define IN_H 42              // TY + 2*HALO
#define SP 43                // sxy row stride in float2 slots (43 mod 16 = 11, odd -> conflict-free)
#define HP 33                // H row stride in float2 slots (33 mod 16 = 1 -> conflict-free)
#define NT 256

#define C1V 1.0e-4f
#define C2V 9.0e-4f
#define EPSV 1.0e-8f

// Normalized 1D Gaussian, sigma=1.5, window 11 (symmetric). Compile-time
// constants -> FFMA with immediate multiplier (rt_SMSP=1 on sm_10x).
__device__ constexpr float GW[11] = {
    0.00102838f, 0.00759876f, 0.03600077f, 0.10936069f, 0.21300553f,
    0.26601172f,
    0.21300553f, 0.10936069f, 0.03600077f, 0.00759876f, 0.00102838f
};

__global__ void zero_out_kernel(float* out) { out[0] = 0.0f; }

__global__ __launch_bounds__(NT) void ssim_kernel(
    const float* __restrict__ x, const float* __restrict__ y,
    float* __restrict__ out, float inv_n)
{
    // Sum/difference transform: convolve s=x+y, d=x-y -> only 4 maps needed.
    __shared__ float2 sxy[IN_H * SP];    // (s, d)            14.4 KB
    __shared__ float2 Hsd[IN_H * HP];    // (Hs, Hd)          11.1 KB
    __shared__ float2 Hs2[IN_H * HP];    // (Hss, Hdd)        11.1 KB
    __shared__ float  red[8];

    const int tid = threadIdx.x;
    const int x0 = blockIdx.x * TX - HALO;
    const int y0 = blockIdx.y * TY - HALO;
    const size_t imgoff = (size_t)blockIdx.z * (IMG_H * IMG_W);
    const float* xb = x + imgoff;
    const float* yb = y + imgoff;

    // ---- Phase 1: load halo tile, store (s,d) pairs (zero pad = SAME) ----
    for (int idx = tid; idx < IN_H * IN_W; idx += NT) {
        int r = idx / IN_W;
        int c = idx - r * IN_W;
        int gy = y0 + r, gx = x0 + c;
        float sv = 0.0f, dv = 0.0f;
        if (gy >= 0 && gy < IMG_H && gx >= 0 && gx < IMG_W) {
            int g = gy * IMG_W + gx;
            float xv = __ldg(xb + g);
            float yv = __ldg(yb + g);
            sv = xv + yv;
            dv = xv - yv;
        }
        sxy[r * SP + c] = make_float2(sv, dv);
    }
    __syncthreads();

    // ---- Phase 2: horizontal pass, scatter form, 4 outputs/unit ----
    // unit u: cg = u / IN_H (8 col-groups of 4), row = u % IN_H (row-fast:
    // lanes hit distinct banks, stride 43).
    for (int u = tid; u < IN_H * 8; u += NT) {
        int cg  = u / IN_H;
        int row = u - cg * IN_H;
        const float2* pin = sxy + row * SP + cg * 4;
        float as[4], ad[4], as2[4], ad2[4];
        #pragma unroll
        for (int k = 0; k < 4; k++) { as[k]=0.f; ad[k]=0.f; as2[k]=0.f; ad2[k]=0.f; }
        #pragma unroll
        for (int i = 0; i < 14; i++) {
            float2 v = pin[i];
            float ss = v.x * v.x;
            float dd = v.y * v.y;
            #pragma unroll
            for (int k = 0; k < 4; k++) {
                const int d = i - k;
                if (d >= 0 && d <= 10) {          // compile-time filtered
                    const float w = GW[d];
                    as[k]  = fmaf(v.x, w, as[k]);
                    ad[k]  = fmaf(v.y, w, ad[k]);
                    as2[k] = fmaf(ss,  w, as2[k]);
                    ad2[k] = fmaf(dd,  w, ad2[k]);
                }
            }
        }
        const int hb = row * HP + cg * 4;
        #pragma unroll
        for (int k = 0; k < 4; k++) {
            Hsd[hb + k] = make_float2(as[k], ad[k]);
            Hs2[hb + k] = make_float2(as2[k], ad2[k]);
        }
    }
    __syncthreads();

    // ---- Phase 3: vertical pass + SSIM, 4 rows per thread ----
    const int c     = tid & 31;
    const int rbase = (tid >> 5) * 4;
    float ms[4], md[4], mss[4], mdd[4];
    #pragma unroll
    for (int k = 0; k < 4; k++) { ms[k]=0.f; md[k]=0.f; mss[k]=0.f; mdd[k]=0.f; }
    #pragma unroll
    for (int j = 0; j < 14; j++) {
        const int hb = (rbase + j) * HP + c;
        float2 h1 = Hsd[hb];
        float2 h2 = Hs2[hb];
        #pragma unroll
        for (int k = 0; k < 4; k++) {
            const int d = j - k;
            if (d >= 0 && d <= 10) {
                const float w = GW[d];
                ms[k]  = fmaf(h1.x, w, ms[k]);
                md[k]  = fmaf(h1.y, w, md[k]);
                mss[k] = fmaf(h2.x, w, mss[k]);
                mdd[k] = fmaf(h2.y, w, mdd[k]);
            }
        }
    }

    float lsum = 0.0f;
    #pragma unroll
    for (int k = 0; k < 4; k++) {
        float mus = ms[k],  mud = md[k];
        float ess = mss[k], edd = mdd[k];
        float mus2 = mus * mus, mud2 = mud * mud;
        float muxy    = 0.25f * (mus2 - mud2);   // mu_x * mu_y
        float mux2py2 = 0.5f  * (mus2 + mud2);   // mu_x^2 + mu_y^2
        float exy     = 0.25f * (ess - edd);     // E[xy]
        float exxpyy  = 0.5f  * (ess + edd);     // E[x^2] + E[y^2]
        float sxyv  = exy - muxy;                // sigma_xy
        float sxpsy = exxpyy - mux2py2;          // sigma_x + sigma_y
        float n = (2.0f * muxy + C1V) * (2.0f * sxyv + C2V);
        float den = (mux2py2 + C1V) * (sxpsy + C2V) + EPSV;
        float v = (1.0f + __fdividef(n, den)) * 0.5f;
        v = fminf(fmaxf(v, 0.0f), 1.0f);
        lsum += v;
    }

    // ---- Reduction: warp shuffle -> smem -> block -> atomic ----
    #pragma unroll
    for (int off = 16; off > 0; off >>= 1)
        lsum += __shfl_xor_sync(0xFFFFFFFFu, lsum, off);
    if ((tid & 31) == 0) red[tid >> 5] = lsum;
    __syncthreads();
    if (tid == 0) {
        float t = 0.0f;
        #pragma unroll
        for (int w = 0; w < 8; w++) t += red[w];
        atomicAdd(out, t * inv_n);
    }
}

extern "C" void kernel_launch(void* const* d_in, const int* in_sizes, int n_in,
                              void* d_out, int out_size)
{
    const float* x = (const float*)d_in[0];
    const float* y = (const float*)d_in[1];
    float* out = (float*)d_out;

    zero_out_kernel<<<1, 1>>>(out);

    dim3 grid(IMG_W / TX, IMG_H / TY, 16 * 3);   // 16 x 16 x 48
    const float inv_n = 1.0f / (float)(16 * 3 * IMG_H * IMG_W);
    ssim_kernel<<<grid, NT>>>(x, y, out, inv_n);
}

// round 5
// speedup vs baseline: 1.5928x; 1.1042x over previous
#include <cuda_runtime.h>

#define IMG_H 512
#define IMG_W 512
#define TX 32
#define TY 32
#define HALO 5
#define IN_W 42              // TX + 2*HALO
#define IN_H 42              // TY + 2*HALO
#define SP 43                // sxy row stride in float2 slots (odd -> conflict-free)
#define HP 33                // H row stride in float2 slots (33 mod 16 = 1 -> conflict-free)
#define NT 256

#define C1V 1.0e-4f
#define C2V 9.0e-4f
#define EPSV 1.0e-8f

// Normalized 1D Gaussian, sigma=1.5, window 11 (symmetric). Compile-time
// constants -> FFMA with immediate multiplier (rt_SMSP=1 on sm_10x).
__device__ constexpr float GW[11] = {
    0.00102838f, 0.00759876f, 0.03600077f, 0.10936069f, 0.21300553f,
    0.26601172f,
    0.21300553f, 0.10936069f, 0.03600077f, 0.00759876f, 0.00102838f
};

__global__ void zero_out_kernel(float* out) { out[0] = 0.0f; }

__global__ __launch_bounds__(NT) void ssim_kernel(
    const float* __restrict__ x, const float* __restrict__ y,
    float* __restrict__ out, float inv_n)
{
    // Sum/difference transform: convolve s=x+y, d=x-y -> only 4 maps needed.
    __shared__ float2 sxy[IN_H * SP];    // (s, d)       14.4 KB
    __shared__ float2 Hsd[IN_H * HP];    // (Hs, Hd)     11.1 KB
    __shared__ float2 Hs2[IN_H * HP];    // (Hss, Hdd)   11.1 KB
    __shared__ float  red[8];

    const int tid = threadIdx.x;
    const int x0 = blockIdx.x * TX - HALO;
    const int y0 = blockIdx.y * TY - HALO;
    const size_t imgoff = (size_t)blockIdx.z * (IMG_H * IMG_W);
    const float* xb = x + imgoff;
    const float* yb = y + imgoff;

    // ---- Phase 1: load halo tile, store (s,d) pairs ----
    const bool interior = (x0 >= 0) & (y0 >= 0) &
                          (x0 + IN_W <= IMG_W) & (y0 + IN_H <= IMG_H);
    if (interior) {
        #pragma unroll
        for (int it = 0; it < 7; it++) {
            int idx = tid + it * NT;
            if (idx < IN_H * IN_W) {          // 1764 total; last iter predicated
                int r = idx / IN_W;
                int c = idx - r * IN_W;
                int g = (y0 + r) * IMG_W + (x0 + c);
                float xv = __ldg(xb + g);
                float yv = __ldg(yb + g);
                sxy[r * SP + c] = make_float2(xv + yv, xv - yv);
            }
        }
    } else {
        #pragma unroll
        for (int it = 0; it < 7; it++) {
            int idx = tid + it * NT;
            if (idx < IN_H * IN_W) {
                int r = idx / IN_W;
                int c = idx - r * IN_W;
                int gy = y0 + r, gx = x0 + c;
                float sv = 0.0f, dv = 0.0f;
                if (gy >= 0 && gy < IMG_H && gx >= 0 && gx < IMG_W) {
                    int g = gy * IMG_W + gx;
                    float xv = __ldg(xb + g);
                    float yv = __ldg(yb + g);
                    sv = xv + yv;
                    dv = xv - yv;
                }
                sxy[r * SP + c] = make_float2(sv, dv);
            }
        }
    }
    __syncthreads();

    // ---- Phase 2: horizontal pass, 168 units x 8 output cols, 2 half-passes ----
    if (tid < IN_H * 4) {
        const int cg  = tid / IN_H;          // 0..3 (8-col groups)
        const int row = tid - cg * IN_H;     // 0..41
        const float2* pin = sxy + row * SP + cg * 8;
        const int hb = row * HP + cg * 8;

        // Half-pass A: mean maps (Hs, Hd)
        {
            float as[8], ad[8];
            #pragma unroll
            for (int i = 0; i < 18; i++) {
                float2 v = pin[i];
                #pragma unroll
                for (int k = 0; k < 8; k++) {
                    const int d = i - k;
                    if (d == 0) {                 // first tap: mul-init (no MOV 0)
                        as[k] = v.x * GW[0];
                        ad[k] = v.y * GW[0];
                    } else if (d > 0 && d <= 10) {
                        const float w = GW[d];
                        as[k] = fmaf(v.x, w, as[k]);
                        ad[k] = fmaf(v.y, w, ad[k]);
                    }
                }
            }
            #pragma unroll
            for (int k = 0; k < 8; k++) Hsd[hb + k] = make_float2(as[k], ad[k]);
        }
        // Half-pass B: second-moment maps (Hss, Hdd)
        {
            float as2[8], ad2[8];
            #pragma unroll
            for (int i = 0; i < 18; i++) {
                float2 v = pin[i];
                float ss = v.x * v.x;
                float dd = v.y * v.y;
                #pragma unroll
                for (int k = 0; k < 8; k++) {
                    const int d = i - k;
                    if (d == 0) {
                        as2[k] = ss * GW[0];
                        ad2[k] = dd * GW[0];
                    } else if (d > 0 && d <= 10) {
                        const float w = GW[d];
                        as2[k] = fmaf(ss, w, as2[k]);
                        ad2[k] = fmaf(dd, w, ad2[k]);
                    }
                }
            }
            #pragma unroll
            for (int k = 0; k < 8; k++) Hs2[hb + k] = make_float2(as2[k], ad2[k]);
        }
    }
    __syncthreads();

    // ---- Phase 3: vertical pass + SSIM, 4 rows per thread ----
    const int c     = tid & 31;
    const int rbase = (tid >> 5) * 4;
    float ms[4], md[4], mss[4], mdd[4];
    const float2* p1 = Hsd + rbase * HP + c;
    const float2* p2 = Hs2 + rbase * HP + c;
    #pragma unroll
    for (int j = 0; j < 14; j++) {
        float2 h1 = p1[j * HP];
        float2 h2 = p2[j * HP];
        #pragma unroll
        for (int k = 0; k < 4; k++) {
            const int d = j - k;
            if (d == 0) {
                ms[k]  = h1.x * GW[0];
                md[k]  = h1.y * GW[0];
                mss[k] = h2.x * GW[0];
                mdd[k] = h2.y * GW[0];
            } else if (d > 0 && d <= 10) {
                const float w = GW[d];
                ms[k]  = fmaf(h1.x, w, ms[k]);
                md[k]  = fmaf(h1.y, w, md[k]);
                mss[k] = fmaf(h2.x, w, mss[k]);
                mdd[k] = fmaf(h2.y, w, mdd[k]);
            }
        }
    }

    float lsum = 0.0f;
    #pragma unroll
    for (int k = 0; k < 4; k++) {
        float mus = ms[k],  mud = md[k];
        float ess = mss[k], edd = mdd[k];
        float mus2 = mus * mus, mud2 = mud * mud;
        float muxy    = 0.25f * (mus2 - mud2);   // mu_x * mu_y
        float mux2py2 = 0.5f  * (mus2 + mud2);   // mu_x^2 + mu_y^2
        float exy     = 0.25f * (ess - edd);     // E[xy]
        float exxpyy  = 0.5f  * (ess + edd);     // E[x^2] + E[y^2]
        float sxyv  = exy - muxy;                // sigma_xy
        float sxpsy = exxpyy - mux2py2;          // sigma_x + sigma_y
        float n = (2.0f * muxy + C1V) * (2.0f * sxyv + C2V);
        float den = (mux2py2 + C1V) * (sxpsy + C2V) + EPSV;
        float v = (1.0f + __fdividef(n, den)) * 0.5f;
        v = fminf(fmaxf(v, 0.0f), 1.0f);
        lsum += v;
    }

    // ---- Reduction: warp shuffle -> smem -> block -> atomic ----
    #pragma unroll
    for (int off = 16; off > 0; off >>= 1)
        lsum += __shfl_xor_sync(0xFFFFFFFFu, lsum, off);
    if ((tid & 31) == 0) red[tid >> 5] = lsum;
    __syncthreads();
    if (tid == 0) {
        float t = 0.0f;
        #pragma unroll
        for (int w = 0; w < 8; w++) t += red[w];
        atomicAdd(out, t * inv_n);
    }
}

extern "C" void kernel_launch(void* const* d_in, const int* in_sizes, int n_in,
                              void* d_out, int out_size)
{
    const float* x = (const float*)d_in[0];
    const float* y = (const float*)d_in[1];
    float* out = (float*)d_out;

    zero_out_kernel<<<1, 1>>>(out);

    dim3 grid(IMG_W / TX, IMG_H / TY, 16 * 3);   // 16 x 16 x 48
    const float inv_n = 1.0f / (float)(16 * 3 * IMG_H * IMG_W);
    ssim_kernel<<<grid, NT>>>(x, y, out, inv_n);
}